// round 1
// baseline (speedup 1.0000x reference)
#include <cuda_runtime.h>

#define NN   40000
#define EE   640000
#define FH   128
#define GG   256
#define NOUT 10

// ---------------- scratch (static device globals; no allocs) ----------------
__device__ int   g_count[NN];
__device__ int   g_ptr[NN + 1];
__device__ int   g_cursor[NN];
__device__ float g_dinv[NN];
__device__ int   g_src[EE];
__device__ float g_buf0[(size_t)NN * FH];
__device__ float g_buf1[(size_t)NN * FH];

// ---------------- CSR build ----------------
__global__ void k_zero_counts() {
    int i = blockIdx.x * blockDim.x + threadIdx.x;
    if (i < NN) g_count[i] = 0;
}

__global__ void k_hist(const int* __restrict__ ei) {
    int e = blockIdx.x * blockDim.x + threadIdx.x;
    if (e < EE) atomicAdd(&g_count[ei[EE + e]], 1);
}

// single-block exclusive scan of g_count -> g_ptr / g_cursor, plus dinv
__global__ void k_scan_dinv() {
    __shared__ int sm[1024];
    int tid = threadIdx.x;
    const int CH = (NN + 1023) / 1024;  // 40
    int base = tid * CH;
    int s = 0;
    for (int i = 0; i < CH; i++) {
        int idx = base + i;
        if (idx < NN) s += g_count[idx];
    }
    sm[tid] = s;
    __syncthreads();
    for (int off = 1; off < 1024; off <<= 1) {
        int v = (tid >= off) ? sm[tid - off] : 0;
        __syncthreads();
        sm[tid] += v;
        __syncthreads();
    }
    int run = sm[tid] - s;  // exclusive prefix
    for (int i = 0; i < CH; i++) {
        int idx = base + i;
        if (idx < NN) {
            int c = g_count[idx];
            g_ptr[idx]    = run;
            g_cursor[idx] = run;
            run += c;
            g_dinv[idx] = rsqrtf((float)(c + 1));  // +1 self-loop, deg>=1 always
        }
    }
    if (tid == 1023) g_ptr[NN] = sm[1023];
}

__global__ void k_scatter(const int* __restrict__ ei) {
    int e = blockIdx.x * blockDim.x + threadIdx.x;
    if (e < EE) {
        int c = ei[EE + e];
        int p = atomicAdd(&g_cursor[c], 1);
        g_src[p] = ei[e];
    }
}

// ---------------- normalized aggregation: Y[i] = dinv[i]*(dinv[i]*X[i] + sum dinv[s]*X[s]) ----------------
__global__ void __launch_bounds__(256) k_agg(const float* __restrict__ X, float* __restrict__ Y) {
    int warp = (blockIdx.x * blockDim.x + threadIdx.x) >> 5;
    int lane = threadIdx.x & 31;
    if (warp >= NN) return;
    int node = warp;
    float di = g_dinv[node];

    const float4* Xs = (const float4*)(X + (size_t)node * FH) + lane;
    float4 xv = *Xs;
    float ax = di * xv.x, ay = di * xv.y, az = di * xv.z, aw = di * xv.w;

    int beg = g_ptr[node], end = g_ptr[node + 1];
    int j = beg;
    for (; j + 4 <= end; j += 4) {
        int s0 = g_src[j], s1 = g_src[j + 1], s2 = g_src[j + 2], s3 = g_src[j + 3];
        float d0 = g_dinv[s0], d1 = g_dinv[s1], d2 = g_dinv[s2], d3 = g_dinv[s3];
        float4 v0 = *((const float4*)(X + (size_t)s0 * FH) + lane);
        float4 v1 = *((const float4*)(X + (size_t)s1 * FH) + lane);
        float4 v2 = *((const float4*)(X + (size_t)s2 * FH) + lane);
        float4 v3 = *((const float4*)(X + (size_t)s3 * FH) + lane);
        ax += d0 * v0.x + d1 * v1.x + d2 * v2.x + d3 * v3.x;
        ay += d0 * v0.y + d1 * v1.y + d2 * v2.y + d3 * v3.y;
        az += d0 * v0.z + d1 * v1.z + d2 * v2.z + d3 * v3.z;
        aw += d0 * v0.w + d1 * v1.w + d2 * v2.w + d3 * v3.w;
    }
    for (; j < end; j++) {
        int s0 = g_src[j];
        float d0 = g_dinv[s0];
        float4 v0 = *((const float4*)(X + (size_t)s0 * FH) + lane);
        ax += d0 * v0.x; ay += d0 * v0.y; az += d0 * v0.z; aw += d0 * v0.w;
    }
    float4 o;
    o.x = ax * di; o.y = ay * di; o.z = az * di; o.w = aw * di;
    *((float4*)(Y + (size_t)node * FH) + lane) = o;
}

// ---------------- GEMM: C = relu(A[M,128] @ W[128,128] + bias), 128x128 tile, 8x8 microtile ----------------
__global__ void __launch_bounds__(256, 1) k_gemm_bias_relu(
    const float* __restrict__ A, const float* __restrict__ W,
    const float* __restrict__ bias, float* __restrict__ C, int M) {
    extern __shared__ float smem[];
    float* As = smem;          // 128*128
    float* Ws = smem + 16384;  // 128*128
    int tid = threadIdx.x;
    int row0 = blockIdx.x * 128;

    // load A tile (zero-pad OOB rows)
    for (int i = tid; i < 4096; i += 256) {
        int r = i >> 5, c = (i & 31) << 2;
        int gr = row0 + r;
        float4 v = make_float4(0.f, 0.f, 0.f, 0.f);
        if (gr < M) v = *(const float4*)(A + (size_t)gr * 128 + c);
        *(float4*)(As + r * 128 + c) = v;
    }
    // load W (full K)
    for (int i = tid; i < 4096; i += 256) {
        int r = i >> 5, c = (i & 31) << 2;
        *(float4*)(Ws + r * 128 + c) = *(const float4*)(W + r * 128 + c);
    }
    __syncthreads();

    int ty = tid >> 4, tx = tid & 15;
    const float* Arow = As + (ty * 8) * 128;
    const float* Wrow = Ws + tx * 8;

    float acc[8][8];
#pragma unroll
    for (int i = 0; i < 8; i++)
#pragma unroll
        for (int jj = 0; jj < 8; jj++) acc[i][jj] = 0.f;

    for (int k = 0; k < 128; k += 4) {
        float4 a[8];
#pragma unroll
        for (int i = 0; i < 8; i++) a[i] = *(const float4*)(Arow + i * 128 + k);
#pragma unroll
        for (int kk = 0; kk < 4; kk++) {
            float4 w0 = *(const float4*)(Wrow + (k + kk) * 128);
            float4 w1 = *(const float4*)(Wrow + (k + kk) * 128 + 4);
            float wv[8] = {w0.x, w0.y, w0.z, w0.w, w1.x, w1.y, w1.z, w1.w};
#pragma unroll
            for (int i = 0; i < 8; i++) {
                float av = (kk == 0) ? a[i].x : (kk == 1) ? a[i].y : (kk == 2) ? a[i].z : a[i].w;
#pragma unroll
                for (int jj = 0; jj < 8; jj++) acc[i][jj] = fmaf(av, wv[jj], acc[i][jj]);
            }
        }
    }

    float bj[8];
#pragma unroll
    for (int jj = 0; jj < 8; jj++) bj[jj] = bias[tx * 8 + jj];
#pragma unroll
    for (int i = 0; i < 8; i++) {
        int gr = row0 + ty * 8 + i;
        if (gr < M) {
            float4 o0, o1;
            o0.x = fmaxf(acc[i][0] + bj[0], 0.f);
            o0.y = fmaxf(acc[i][1] + bj[1], 0.f);
            o0.z = fmaxf(acc[i][2] + bj[2], 0.f);
            o0.w = fmaxf(acc[i][3] + bj[3], 0.f);
            o1.x = fmaxf(acc[i][4] + bj[4], 0.f);
            o1.y = fmaxf(acc[i][5] + bj[5], 0.f);
            o1.z = fmaxf(acc[i][6] + bj[6], 0.f);
            o1.w = fmaxf(acc[i][7] + bj[7], 0.f);
            *(float4*)(C + (size_t)gr * 128 + tx * 8)     = o0;
            *(float4*)(C + (size_t)gr * 128 + tx * 8 + 4) = o1;
        }
    }
}

// ---------------- mean pool (batch sorted) + FC + log_softmax ----------------
__device__ __forceinline__ int lower_bound_i(const int* __restrict__ b, int n, int key) {
    int lo = 0, hi = n;
    while (lo < hi) {
        int mid = (lo + hi) >> 1;
        if (b[mid] < key) lo = mid + 1; else hi = mid;
    }
    return lo;
}

__global__ void __launch_bounds__(128) k_pool_fc(
    const float* __restrict__ H2, const int* __restrict__ batch,
    const float* __restrict__ Wfc, const float* __restrict__ bfc,
    float* __restrict__ out) {
    int g = blockIdx.x;
    int tid = threadIdx.x;
    __shared__ float pooled[FH];
    __shared__ float logit[NOUT];
    __shared__ int range[2];

    if (tid == 0) {
        range[0] = lower_bound_i(batch, NN, g);
        range[1] = lower_bound_i(batch, NN, g + 1);
    }
    __syncthreads();
    int lo = range[0], hi = range[1];

    float s = 0.f;
    for (int n = lo; n < hi; n++) s += H2[(size_t)n * FH + tid];
    pooled[tid] = s / fmaxf((float)(hi - lo), 1.0f);
    __syncthreads();

    if (tid < NOUT) {
        float acc = bfc[tid];
        for (int k = 0; k < FH; k++) acc = fmaf(pooled[k], Wfc[k * NOUT + tid], acc);
        logit[tid] = acc;
    }
    __syncthreads();

    if (tid == 0) {
        float m = -1e30f;
        for (int o = 0; o < NOUT; o++) m = fmaxf(m, logit[o]);
        float se = 0.f;
        for (int o = 0; o < NOUT; o++) se += expf(logit[o] - m);
        float lse = m + logf(se);
        for (int o = 0; o < NOUT; o++) out[g * NOUT + o] = logit[o] - lse;
    }
}

// ---------------- launch ----------------
extern "C" void kernel_launch(void* const* d_in, const int* in_sizes, int n_in,
                              void* d_out, int out_size) {
    const float* x    = (const float*)d_in[0];
    const int*   ei   = (const int*)d_in[1];
    const int*   batc = (const int*)d_in[2];
    const float* W1   = (const float*)d_in[3];
    const float* b1   = (const float*)d_in[4];
    const float* W2   = (const float*)d_in[5];
    const float* b2   = (const float*)d_in[6];
    const float* Wfc  = (const float*)d_in[7];
    const float* bfc  = (const float*)d_in[8];
    float* out = (float*)d_out;

    float *buf0, *buf1;
    cudaGetSymbolAddress((void**)&buf0, g_buf0);
    cudaGetSymbolAddress((void**)&buf1, g_buf1);

    cudaFuncSetAttribute(k_gemm_bias_relu,
                         cudaFuncAttributeMaxDynamicSharedMemorySize, 131072);

    // CSR build (keyed by destination col)
    k_zero_counts<<<(NN + 255) / 256, 256>>>();
    k_hist<<<(EE + 255) / 256, 256>>>(ei);
    k_scan_dinv<<<1, 1024>>>();
    k_scatter<<<(EE + 255) / 256, 256>>>(ei);

    // conv1: agg(x) -> buf0 ; relu(buf0 @ W1 + b1) -> buf1
    k_agg<<<NN / 8, 256>>>(x, buf0);
    k_gemm_bias_relu<<<(NN + 127) / 128, 256, 131072>>>(buf0, W1, b1, buf1, NN);

    // conv2: agg(h1) -> buf0 ; relu(buf0 @ W2 + b2) -> buf1
    k_agg<<<NN / 8, 256>>>(buf1, buf0);
    k_gemm_bias_relu<<<(NN + 127) / 128, 256, 131072>>>(buf0, W2, b2, buf1, NN);

    // mean pool + fc + log_softmax
    k_pool_fc<<<GG, 128>>>(buf1, batc, Wfc, bfc, out);
}

// round 3
// speedup vs baseline: 1.1995x; 1.1995x over previous
#include <cuda_runtime.h>
#include <cstdint>

#define NN   40000
#define EE   640000
#define FH   128
#define GG   256
#define NOUT 10

// ---------------- scratch (static device globals; no allocs) ----------------
__device__ int   g_count[NN];
__device__ int   g_ptr[NN + 1];
__device__ int   g_cursor[NN];
__device__ float g_dinv[NN];
__device__ int   g_src[EE];
__device__ float g_buf0[(size_t)NN * FH];
__device__ float g_buf1[(size_t)NN * FH];

__device__ __forceinline__ uint32_t f2tf32(float x) {
    uint32_t r; asm("cvt.rna.tf32.f32 %0, %1;" : "=r"(r) : "f"(x)); return r;
}

// ---------------- CSR build ----------------
__global__ void k_zero_counts() {
    int i = blockIdx.x * blockDim.x + threadIdx.x;
    if (i < NN) g_count[i] = 0;
}

__global__ void k_hist(const int* __restrict__ ei) {
    int e = blockIdx.x * blockDim.x + threadIdx.x;
    if (e < EE) atomicAdd(&g_count[ei[EE + e]], 1);
}

__global__ void k_scan_dinv() {
    __shared__ int sm[1024];
    int tid = threadIdx.x;
    const int CH = (NN + 1023) / 1024;
    int base = tid * CH;
    int s = 0;
    for (int i = 0; i < CH; i++) {
        int idx = base + i;
        if (idx < NN) s += g_count[idx];
    }
    sm[tid] = s;
    __syncthreads();
    for (int off = 1; off < 1024; off <<= 1) {
        int v = (tid >= off) ? sm[tid - off] : 0;
        __syncthreads();
        sm[tid] += v;
        __syncthreads();
    }
    int run = sm[tid] - s;
    for (int i = 0; i < CH; i++) {
        int idx = base + i;
        if (idx < NN) {
            int c = g_count[idx];
            g_ptr[idx]    = run;
            g_cursor[idx] = run;
            run += c;
            g_dinv[idx] = rsqrtf((float)(c + 1));
        }
    }
    if (tid == 1023) g_ptr[NN] = sm[1023];
}

__global__ void k_scatter(const int* __restrict__ ei) {
    int e = blockIdx.x * blockDim.x + threadIdx.x;
    if (e < EE) {
        int c = ei[EE + e];
        int p = atomicAdd(&g_cursor[c], 1);
        g_src[p] = ei[e];
    }
}

// ---------------- normalized aggregation ----------------
__global__ void __launch_bounds__(256) k_agg(const float* __restrict__ X, float* __restrict__ Y) {
    int warp = (blockIdx.x * blockDim.x + threadIdx.x) >> 5;
    int lane = threadIdx.x & 31;
    if (warp >= NN) return;
    int node = warp;
    float di = g_dinv[node];

    float4 xv = *((const float4*)(X + (size_t)node * FH) + lane);
    float ax = di * xv.x, ay = di * xv.y, az = di * xv.z, aw = di * xv.w;

    int beg = g_ptr[node], end = g_ptr[node + 1];
    int j = beg;
    for (; j + 4 <= end; j += 4) {
        int s0 = g_src[j], s1 = g_src[j + 1], s2 = g_src[j + 2], s3 = g_src[j + 3];
        float d0 = g_dinv[s0], d1 = g_dinv[s1], d2 = g_dinv[s2], d3 = g_dinv[s3];
        float4 v0 = *((const float4*)(X + (size_t)s0 * FH) + lane);
        float4 v1 = *((const float4*)(X + (size_t)s1 * FH) + lane);
        float4 v2 = *((const float4*)(X + (size_t)s2 * FH) + lane);
        float4 v3 = *((const float4*)(X + (size_t)s3 * FH) + lane);
        ax += d0 * v0.x + d1 * v1.x + d2 * v2.x + d3 * v3.x;
        ay += d0 * v0.y + d1 * v1.y + d2 * v2.y + d3 * v3.y;
        az += d0 * v0.z + d1 * v1.z + d2 * v2.z + d3 * v3.z;
        aw += d0 * v0.w + d1 * v1.w + d2 * v2.w + d3 * v3.w;
    }
    for (; j < end; j++) {
        int s0 = g_src[j];
        float d0 = g_dinv[s0];
        float4 v0 = *((const float4*)(X + (size_t)s0 * FH) + lane);
        ax += d0 * v0.x; ay += d0 * v0.y; az += d0 * v0.z; aw += d0 * v0.w;
    }
    float4 o;
    o.x = ax * di; o.y = ay * di; o.z = az * di; o.w = aw * di;
    *((float4*)(Y + (size_t)node * FH) + lane) = o;
}

// ---------------- tf32 mma.sync GEMM: C = relu(A[M,128] @ W[128,128] + bias) ----------------
// 256 threads, 128x128 tile, warp grid 2(M) x 4(N), each warp 64x32 via m16n8k8.
#define AS_STRIDE 132   // bank = (4*row + col) % 32 -> A frag loads conflict-free
#define BS_STRIDE 136   // bank = (8*row + col) % 32 -> B frag loads conflict-free
#define SM_GEMM_BYTES ((128 * AS_STRIDE + 128 * BS_STRIDE) * 4)

__device__ __forceinline__ void mma_tf32(float* c, uint32_t a0, uint32_t a1, uint32_t a2,
                                         uint32_t a3, uint32_t b0, uint32_t b1) {
    asm volatile(
        "mma.sync.aligned.m16n8k8.row.col.f32.tf32.tf32.f32 "
        "{%0,%1,%2,%3}, {%4,%5,%6,%7}, {%8,%9}, {%0,%1,%2,%3};"
        : "+f"(c[0]), "+f"(c[1]), "+f"(c[2]), "+f"(c[3])
        : "r"(a0), "r"(a1), "r"(a2), "r"(a3), "r"(b0), "r"(b1));
}

__global__ void __launch_bounds__(256, 1) k_gemm_mma(
    const float* __restrict__ A, const float* __restrict__ W,
    const float* __restrict__ bias, float* __restrict__ C, int M) {
    extern __shared__ float sm[];
    float* As = sm;                            // [128][AS_STRIDE]
    float* Bs = sm + 128 * AS_STRIDE;          // [128][BS_STRIDE], layout [k][n]
    int tid = threadIdx.x;
    int row0 = blockIdx.x * 128;

    // load A tile (tf32-rounded, zero-pad OOB rows)
    for (int i = tid; i < 4096; i += 256) {
        int r = i >> 5, c = (i & 31) << 2;
        int gr = row0 + r;
        float4 v = make_float4(0.f, 0.f, 0.f, 0.f);
        if (gr < M) v = *(const float4*)(A + (size_t)gr * 128 + c);
        float4 t;
        t.x = __uint_as_float(f2tf32(v.x));
        t.y = __uint_as_float(f2tf32(v.y));
        t.z = __uint_as_float(f2tf32(v.z));
        t.w = __uint_as_float(f2tf32(v.w));
        *(float4*)(As + r * AS_STRIDE + c) = t;
    }
    // load W [k][n] (tf32-rounded)
    for (int i = tid; i < 4096; i += 256) {
        int r = i >> 5, c = (i & 31) << 2;
        float4 v = *(const float4*)(W + (size_t)r * 128 + c);
        float4 t;
        t.x = __uint_as_float(f2tf32(v.x));
        t.y = __uint_as_float(f2tf32(v.y));
        t.z = __uint_as_float(f2tf32(v.z));
        t.w = __uint_as_float(f2tf32(v.w));
        *(float4*)(Bs + r * BS_STRIDE + c) = t;
    }
    __syncthreads();

    int wid = tid >> 5, lane = tid & 31;
    int wm = (wid >> 2) * 64;       // warp M offset (0 or 64)
    int wn = (wid & 3) * 32;        // warp N offset (0,32,64,96)
    int g = lane >> 2, tg = lane & 3;

    float acc[4][4][4];
#pragma unroll
    for (int mt = 0; mt < 4; mt++)
#pragma unroll
        for (int nt = 0; nt < 4; nt++)
#pragma unroll
            for (int r = 0; r < 4; r++) acc[mt][nt][r] = 0.f;

#pragma unroll
    for (int k0 = 0; k0 < 128; k0 += 8) {
        uint32_t af[4][4];
#pragma unroll
        for (int mt = 0; mt < 4; mt++) {
            const float* ap = As + (wm + mt * 16) * AS_STRIDE + k0;
            af[mt][0] = __float_as_uint(ap[g * AS_STRIDE + tg]);
            af[mt][1] = __float_as_uint(ap[(g + 8) * AS_STRIDE + tg]);
            af[mt][2] = __float_as_uint(ap[g * AS_STRIDE + tg + 4]);
            af[mt][3] = __float_as_uint(ap[(g + 8) * AS_STRIDE + tg + 4]);
        }
        uint32_t bf[4][2];
#pragma unroll
        for (int nt = 0; nt < 4; nt++) {
            const float* bp = Bs + k0 * BS_STRIDE + wn + nt * 8;
            bf[nt][0] = __float_as_uint(bp[tg * BS_STRIDE + g]);
            bf[nt][1] = __float_as_uint(bp[(tg + 4) * BS_STRIDE + g]);
        }
#pragma unroll
        for (int mt = 0; mt < 4; mt++)
#pragma unroll
            for (int nt = 0; nt < 4; nt++)
                mma_tf32(acc[mt][nt], af[mt][0], af[mt][1], af[mt][2], af[mt][3],
                         bf[nt][0], bf[nt][1]);
    }

    // epilogue: bias + relu, float2 stores (cols tig*2, tig*2+1)
#pragma unroll
    for (int nt = 0; nt < 4; nt++) {
        int cidx = wn + nt * 8 + tg * 2;
        float bb0 = __ldg(bias + cidx), bb1 = __ldg(bias + cidx + 1);
#pragma unroll
        for (int mt = 0; mt < 4; mt++) {
            int r0 = row0 + wm + mt * 16 + g;
            if (r0 < M) {
                float2 o;
                o.x = fmaxf(acc[mt][nt][0] + bb0, 0.f);
                o.y = fmaxf(acc[mt][nt][1] + bb1, 0.f);
                *(float2*)(C + (size_t)r0 * 128 + cidx) = o;
            }
            int r1 = r0 + 8;
            if (r1 < M) {
                float2 o;
                o.x = fmaxf(acc[mt][nt][2] + bb0, 0.f);
                o.y = fmaxf(acc[mt][nt][3] + bb1, 0.f);
                *(float2*)(C + (size_t)r1 * 128 + cidx) = o;
            }
        }
    }
}

// ---------------- mean pool (batch sorted) + FC + log_softmax ----------------
__device__ __forceinline__ int lower_bound_i(const int* __restrict__ b, int n, int key) {
    int lo = 0, hi = n;
    while (lo < hi) {
        int mid = (lo + hi) >> 1;
        if (b[mid] < key) lo = mid + 1; else hi = mid;
    }
    return lo;
}

__global__ void __launch_bounds__(128) k_pool_fc(
    const float* __restrict__ H2, const int* __restrict__ batch,
    const float* __restrict__ Wfc, const float* __restrict__ bfc,
    float* __restrict__ out) {
    int g = blockIdx.x;
    int tid = threadIdx.x;
    __shared__ float pooled[FH];
    __shared__ float logit[NOUT];
    __shared__ int range[2];

    if (tid == 0) {
        range[0] = lower_bound_i(batch, NN, g);
        range[1] = lower_bound_i(batch, NN, g + 1);
    }
    __syncthreads();
    int lo = range[0], hi = range[1];

    float s = 0.f;
    for (int n = lo; n < hi; n++) s += H2[(size_t)n * FH + tid];
    pooled[tid] = s / fmaxf((float)(hi - lo), 1.0f);
    __syncthreads();

    if (tid < NOUT) {
        float acc = bfc[tid];
        for (int k = 0; k < FH; k++) acc = fmaf(pooled[k], Wfc[k * NOUT + tid], acc);
        logit[tid] = acc;
    }
    __syncthreads();

    if (tid == 0) {
        float m = -1e30f;
        for (int o = 0; o < NOUT; o++) m = fmaxf(m, logit[o]);
        float se = 0.f;
        for (int o = 0; o < NOUT; o++) se += expf(logit[o] - m);
        float lse = m + logf(se);
        for (int o = 0; o < NOUT; o++) out[g * NOUT + o] = logit[o] - lse;
    }
}

// ---------------- launch ----------------
extern "C" void kernel_launch(void* const* d_in, const int* in_sizes, int n_in,
                              void* d_out, int out_size) {
    const float* x    = (const float*)d_in[0];
    const int*   ei   = (const int*)d_in[1];
    const int*   batc = (const int*)d_in[2];
    const float* W1   = (const float*)d_in[3];
    const float* b1   = (const float*)d_in[4];
    const float* W2   = (const float*)d_in[5];
    const float* b2   = (const float*)d_in[6];
    const float* Wfc  = (const float*)d_in[7];
    const float* bfc  = (const float*)d_in[8];
    float* out = (float*)d_out;

    float *buf0, *buf1;
    cudaGetSymbolAddress((void**)&buf0, g_buf0);
    cudaGetSymbolAddress((void**)&buf1, g_buf1);

    cudaFuncSetAttribute(k_gemm_mma,
                         cudaFuncAttributeMaxDynamicSharedMemorySize, SM_GEMM_BYTES);

    // CSR build (keyed by destination col)
    k_zero_counts<<<(NN + 255) / 256, 256>>>();
    k_hist<<<(EE + 255) / 256, 256>>>(ei);
    k_scan_dinv<<<1, 1024>>>();
    k_scatter<<<(EE + 255) / 256, 256>>>(ei);

    int gblocks = (NN + 127) / 128;

    // conv1: agg(x) -> buf0 ; relu(buf0 @ W1 + b1) -> buf1
    k_agg<<<NN / 8, 256>>>(x, buf0);
    k_gemm_mma<<<gblocks, 256, SM_GEMM_BYTES>>>(buf0, W1, b1, buf1, NN);

    // conv2: agg(h1) -> buf0 ; relu(buf0 @ W2 + b2) -> buf1
    k_agg<<<NN / 8, 256>>>(buf1, buf0);
    k_gemm_mma<<<gblocks, 256, SM_GEMM_BYTES>>>(buf0, W2, b2, buf1, NN);

    // mean pool + fc + log_softmax
    k_pool_fc<<<GG, 128>>>(buf1, batc, Wfc, bfc, out);
}

// round 4
// speedup vs baseline: 1.4640x; 1.2206x over previous
#include <cuda_runtime.h>
#include <cuda_fp16.h>
#include <cstdint>

#define NN   40000
#define EE   640000
#define FH   128
#define GG   256
#define NOUT 10

// ---------------- scratch (static device globals; no allocs) ----------------
__device__ int   g_count[NN];
__device__ int   g_ptr[NN + 1];
__device__ int   g_cursor[NN];
__device__ float g_dinv[NN];
__device__ int   g_src[EE];
__device__ float g_buf0[(size_t)NN * FH];  // reused as half buffers
__device__ float g_buf1[(size_t)NN * FH];

__device__ __forceinline__ uint32_t h2u(__half2 h) { return *reinterpret_cast<uint32_t*>(&h); }
__device__ __forceinline__ __half2  u2h(uint32_t u) { return *reinterpret_cast<__half2*>(&u); }

// ---------------- CSR build ----------------
__global__ void k_zero_counts() {
    int i = blockIdx.x * blockDim.x + threadIdx.x;
    if (i < NN) g_count[i] = 0;
}

__global__ void k_hist(const int* __restrict__ ei) {
    int e = blockIdx.x * blockDim.x + threadIdx.x;
    if (e < EE) atomicAdd(&g_count[ei[EE + e]], 1);
}

__global__ void k_scan_dinv() {
    __shared__ int sm[1024];
    int tid = threadIdx.x;
    const int CH = (NN + 1023) / 1024;
    int base = tid * CH;
    int s = 0;
    for (int i = 0; i < CH; i++) {
        int idx = base + i;
        if (idx < NN) s += g_count[idx];
    }
    sm[tid] = s;
    __syncthreads();
    for (int off = 1; off < 1024; off <<= 1) {
        int v = (tid >= off) ? sm[tid - off] : 0;
        __syncthreads();
        sm[tid] += v;
        __syncthreads();
    }
    int run = sm[tid] - s;
    for (int i = 0; i < CH; i++) {
        int idx = base + i;
        if (idx < NN) {
            int c = g_count[idx];
            g_ptr[idx]    = run;
            g_cursor[idx] = run;
            run += c;
            g_dinv[idx] = rsqrtf((float)(c + 1));
        }
    }
    if (tid == 1023) g_ptr[NN] = sm[1023];
}

__global__ void k_scatter(const int* __restrict__ ei) {
    int e = blockIdx.x * blockDim.x + threadIdx.x;
    if (e < EE) {
        int c = ei[EE + e];
        int p = atomicAdd(&g_cursor[c], 1);
        g_src[p] = ei[e];
    }
}

// ---------------- fp16 mma GEMM: C[M,128](fp16) = A[M,128] @ W[128,128] ----------------
// A input is fp32 (a_fp32=1, converted on load) or fp16. W is fp32, transposed
// into smem [n][k] fp16. 256 threads, warp grid 2(M) x 4(N), m16n8k16.
#define AHS 136   // A smem stride in halfs -> conflict-free frag loads + uint2 stores
#define BHS 136   // B smem stride in halfs
#define SMEM_GEMM ((128 * AHS + 128 * BHS) * 2)

__device__ __forceinline__ void mma_f16(float* c, uint32_t a0, uint32_t a1, uint32_t a2,
                                        uint32_t a3, uint32_t b0, uint32_t b1) {
    asm volatile(
        "mma.sync.aligned.m16n8k16.row.col.f32.f16.f16.f32 "
        "{%0,%1,%2,%3}, {%4,%5,%6,%7}, {%8,%9}, {%0,%1,%2,%3};"
        : "+f"(c[0]), "+f"(c[1]), "+f"(c[2]), "+f"(c[3])
        : "r"(a0), "r"(a1), "r"(a2), "r"(a3), "r"(b0), "r"(b1));
}

__global__ void __launch_bounds__(256, 2) k_gemm_h(
    const void* __restrict__ Ain, int a_fp32,
    const float* __restrict__ W, __half* __restrict__ C, int M) {
    extern __shared__ __half sh[];
    __half* As = sh;
    __half* Bs = sh + 128 * AHS;
    int tid = threadIdx.x;
    int row0 = blockIdx.x * 128;

    // ---- A tile -> smem fp16 (zero-pad OOB rows) ----
    if (a_fp32) {
        const float* A = (const float*)Ain;
        for (int i = tid; i < 4096; i += 256) {
            int r = i >> 5, c = (i & 31) << 2;
            int gr = row0 + r;
            float4 v = make_float4(0.f, 0.f, 0.f, 0.f);
            if (gr < M) v = *(const float4*)(A + (size_t)gr * 128 + c);
            uint2 u;
            u.x = h2u(__floats2half2_rn(v.x, v.y));
            u.y = h2u(__floats2half2_rn(v.z, v.w));
            *(uint2*)(As + r * AHS + c) = u;
        }
    } else {
        const __half* A = (const __half*)Ain;
        for (int i = tid; i < 4096; i += 256) {
            int r = i >> 5, c = (i & 31) << 2;
            int gr = row0 + r;
            uint2 u = make_uint2(0u, 0u);
            if (gr < M) u = *(const uint2*)(A + (size_t)gr * 128 + c);
            *(uint2*)(As + r * AHS + c) = u;
        }
    }

    // ---- W -> Bs[n][k] fp16 transposed; lanes vary k so stores are conflict-free ----
    for (int t = 0; t < 8; t++) {
        int idx = tid + t * 256;                       // 0..2047
        int k2 = (idx & 31) | (((idx >> 5) & 1) << 5); // 0..63, low 5 bits = lane
        int n4 = (idx >> 6) << 2;                      // 0,4,...,124
        int k = k2 * 2;
        const float* w0 = W + (size_t)k * 128 + n4;
        float4 r0 = *(const float4*)w0;
        float4 r1 = *(const float4*)(w0 + 128);
        *(uint32_t*)(Bs + (n4 + 0) * BHS + k) = h2u(__floats2half2_rn(r0.x, r1.x));
        *(uint32_t*)(Bs + (n4 + 1) * BHS + k) = h2u(__floats2half2_rn(r0.y, r1.y));
        *(uint32_t*)(Bs + (n4 + 2) * BHS + k) = h2u(__floats2half2_rn(r0.z, r1.z));
        *(uint32_t*)(Bs + (n4 + 3) * BHS + k) = h2u(__floats2half2_rn(r0.w, r1.w));
    }
    __syncthreads();

    int wid = tid >> 5, lane = tid & 31;
    int wm = (wid >> 2) * 64;
    int wn = (wid & 3) * 32;
    int g = lane >> 2, tg = lane & 3;

    float acc[4][4][4];
#pragma unroll
    for (int mt = 0; mt < 4; mt++)
#pragma unroll
        for (int nt = 0; nt < 4; nt++)
#pragma unroll
            for (int r = 0; r < 4; r++) acc[mt][nt][r] = 0.f;

#pragma unroll
    for (int k0 = 0; k0 < 128; k0 += 16) {
        uint32_t af[4][4];
#pragma unroll
        for (int mt = 0; mt < 4; mt++) {
            const __half* ap = As + (wm + mt * 16) * AHS + k0 + tg * 2;
            af[mt][0] = *(const uint32_t*)(ap + g * AHS);
            af[mt][1] = *(const uint32_t*)(ap + (g + 8) * AHS);
            af[mt][2] = *(const uint32_t*)(ap + g * AHS + 8);
            af[mt][3] = *(const uint32_t*)(ap + (g + 8) * AHS + 8);
        }
        uint32_t bf[4][2];
#pragma unroll
        for (int nt = 0; nt < 4; nt++) {
            const __half* bp = Bs + (wn + nt * 8 + g) * BHS + k0 + tg * 2;
            bf[nt][0] = *(const uint32_t*)(bp);
            bf[nt][1] = *(const uint32_t*)(bp + 8);
        }
#pragma unroll
        for (int mt = 0; mt < 4; mt++)
#pragma unroll
            for (int nt = 0; nt < 4; nt++)
                mma_f16(acc[mt][nt], af[mt][0], af[mt][1], af[mt][2], af[mt][3],
                        bf[nt][0], bf[nt][1]);
    }

    // ---- epilogue: fp16 store (no bias/relu; folded into agg) ----
#pragma unroll
    for (int nt = 0; nt < 4; nt++) {
        int col = wn + nt * 8 + tg * 2;
#pragma unroll
        for (int mt = 0; mt < 4; mt++) {
            int r0 = row0 + wm + mt * 16 + g;
            if (r0 < M)
                *(uint32_t*)(C + (size_t)r0 * 128 + col) =
                    h2u(__floats2half2_rn(acc[mt][nt][0], acc[mt][nt][1]));
            int r1 = r0 + 8;
            if (r1 < M)
                *(uint32_t*)(C + (size_t)r1 * 128 + col) =
                    h2u(__floats2half2_rn(acc[mt][nt][2], acc[mt][nt][3]));
        }
    }
}

// ---------------- fp16 aggregation + bias + relu ----------------
// Hout[i] = relu(dinv[i] * (dinv[i]*P[i] + sum_s dinv[s]*P[s]) + bias)
__global__ void __launch_bounds__(256) k_agg_h(
    const __half* __restrict__ P, __half* __restrict__ Hout,
    const float* __restrict__ bias) {
    int warp = (blockIdx.x * blockDim.x + threadIdx.x) >> 5;
    int lane = threadIdx.x & 31;
    if (warp >= NN) return;
    int node = warp;
    int c4 = lane * 4;
    float di = g_dinv[node];

    uint2 sv = *(const uint2*)(P + (size_t)node * FH + c4);
    float2 f0 = __half22float2(u2h(sv.x));
    float2 f1 = __half22float2(u2h(sv.y));
    float ax = di * f0.x, ay = di * f0.y, az = di * f1.x, aw = di * f1.y;

    int beg = g_ptr[node], end = g_ptr[node + 1];
    int j = beg;
    for (; j + 4 <= end; j += 4) {
        int s0 = g_src[j], s1 = g_src[j + 1], s2 = g_src[j + 2], s3 = g_src[j + 3];
        float d0 = g_dinv[s0], d1 = g_dinv[s1], d2 = g_dinv[s2], d3 = g_dinv[s3];
        uint2 v0 = *(const uint2*)(P + (size_t)s0 * FH + c4);
        uint2 v1 = *(const uint2*)(P + (size_t)s1 * FH + c4);
        uint2 v2 = *(const uint2*)(P + (size_t)s2 * FH + c4);
        uint2 v3 = *(const uint2*)(P + (size_t)s3 * FH + c4);
        float2 a0 = __half22float2(u2h(v0.x)), b0 = __half22float2(u2h(v0.y));
        float2 a1 = __half22float2(u2h(v1.x)), b1 = __half22float2(u2h(v1.y));
        float2 a2 = __half22float2(u2h(v2.x)), b2 = __half22float2(u2h(v2.y));
        float2 a3 = __half22float2(u2h(v3.x)), b3 = __half22float2(u2h(v3.y));
        ax += d0 * a0.x + d1 * a1.x + d2 * a2.x + d3 * a3.x;
        ay += d0 * a0.y + d1 * a1.y + d2 * a2.y + d3 * a3.y;
        az += d0 * b0.x + d1 * b1.x + d2 * b2.x + d3 * b3.x;
        aw += d0 * b0.y + d1 * b1.y + d2 * b2.y + d3 * b3.y;
    }
    for (; j < end; j++) {
        int s0 = g_src[j];
        float d0 = g_dinv[s0];
        uint2 v0 = *(const uint2*)(P + (size_t)s0 * FH + c4);
        float2 a0 = __half22float2(u2h(v0.x)), b0 = __half22float2(u2h(v0.y));
        ax += d0 * a0.x; ay += d0 * a0.y; az += d0 * b0.x; aw += d0 * b0.y;
    }

    float4 bb = *(const float4*)(bias + c4);
    float ox = fmaxf(fmaf(ax, di, bb.x), 0.f);
    float oy = fmaxf(fmaf(ay, di, bb.y), 0.f);
    float oz = fmaxf(fmaf(az, di, bb.z), 0.f);
    float ow = fmaxf(fmaf(aw, di, bb.w), 0.f);
    uint2 o;
    o.x = h2u(__floats2half2_rn(ox, oy));
    o.y = h2u(__floats2half2_rn(oz, ow));
    *(uint2*)(Hout + (size_t)node * FH + c4) = o;
}

// ---------------- mean pool (batch sorted) + FC + log_softmax ----------------
__device__ __forceinline__ int lower_bound_i(const int* __restrict__ b, int n, int key) {
    int lo = 0, hi = n;
    while (lo < hi) {
        int mid = (lo + hi) >> 1;
        if (b[mid] < key) lo = mid + 1; else hi = mid;
    }
    return lo;
}

__global__ void __launch_bounds__(128) k_pool_fc(
    const __half* __restrict__ H2, const int* __restrict__ batch,
    const float* __restrict__ Wfc, const float* __restrict__ bfc,
    float* __restrict__ out) {
    int g = blockIdx.x;
    int tid = threadIdx.x;
    __shared__ float pooled[FH];
    __shared__ float logit[NOUT];
    __shared__ int range[2];

    if (tid == 0) {
        range[0] = lower_bound_i(batch, NN, g);
        range[1] = lower_bound_i(batch, NN, g + 1);
    }
    __syncthreads();
    int lo = range[0], hi = range[1];

    float s = 0.f;
    for (int n = lo; n < hi; n++) s += __half2float(H2[(size_t)n * FH + tid]);
    pooled[tid] = s / fmaxf((float)(hi - lo), 1.0f);
    __syncthreads();

    if (tid < NOUT) {
        float acc = bfc[tid];
        for (int k = 0; k < FH; k++) acc = fmaf(pooled[k], Wfc[k * NOUT + tid], acc);
        logit[tid] = acc;
    }
    __syncthreads();

    if (tid == 0) {
        float m = -1e30f;
        for (int o = 0; o < NOUT; o++) m = fmaxf(m, logit[o]);
        float se = 0.f;
        for (int o = 0; o < NOUT; o++) se += expf(logit[o] - m);
        float lse = m + logf(se);
        for (int o = 0; o < NOUT; o++) out[g * NOUT + o] = logit[o] - lse;
    }
}

// ---------------- launch ----------------
struct HxRes {
    cudaStream_t s2;
    cudaEvent_t e0, e1;
    HxRes() {
        cudaStreamCreateWithFlags(&s2, cudaStreamNonBlocking);
        cudaEventCreateWithFlags(&e0, cudaEventDisableTiming);
        cudaEventCreateWithFlags(&e1, cudaEventDisableTiming);
    }
};

extern "C" void kernel_launch(void* const* d_in, const int* in_sizes, int n_in,
                              void* d_out, int out_size) {
    static HxRes hx;  // created on first (non-capture) call; same work every call

    const float* x    = (const float*)d_in[0];
    const int*   ei   = (const int*)d_in[1];
    const int*   batc = (const int*)d_in[2];
    const float* W1   = (const float*)d_in[3];
    const float* b1   = (const float*)d_in[4];
    const float* W2   = (const float*)d_in[5];
    const float* b2   = (const float*)d_in[6];
    const float* Wfc  = (const float*)d_in[7];
    const float* bfc  = (const float*)d_in[8];
    float* out = (float*)d_out;

    void *p0, *p1;
    cudaGetSymbolAddress(&p0, g_buf0);
    cudaGetSymbolAddress(&p1, g_buf1);
    __half* bufP = (__half*)p0;
    __half* bufH = (__half*)p1;

    cudaFuncSetAttribute(k_gemm_h,
                         cudaFuncAttributeMaxDynamicSharedMemorySize, SMEM_GEMM);

    int gblocks = (NN + 127) / 128;

    // fork: GEMM1 (P1 = X @ W1) is independent of the CSR build
    cudaEventRecord(hx.e0, 0);
    cudaStreamWaitEvent(hx.s2, hx.e0, 0);
    k_gemm_h<<<gblocks, 256, SMEM_GEMM, hx.s2>>>(x, 1, W1, bufP, NN);
    cudaEventRecord(hx.e1, hx.s2);

    // CSR build on the main (capturing) stream
    k_zero_counts<<<(NN + 255) / 256, 256>>>();
    k_hist<<<(EE + 255) / 256, 256>>>(ei);
    k_scan_dinv<<<1, 1024>>>();
    k_scatter<<<(EE + 255) / 256, 256>>>(ei);

    // join, then: h1 = relu(agg(P1) + b1)
    cudaStreamWaitEvent(0, hx.e1, 0);
    k_agg_h<<<NN / 8, 256>>>(bufP, bufH, b1);

    // layer 2: P2 = h1 @ W2 ; h2 = relu(agg(P2) + b2)
    k_gemm_h<<<gblocks, 256, SMEM_GEMM>>>(bufH, 0, W2, bufP, NN);
    k_agg_h<<<NN / 8, 256>>>(bufP, bufH, b2);

    // mean pool + fc + log_softmax
    k_pool_fc<<<GG, 128>>>(bufH, batc, Wfc, bfc, out);
}

// round 5
// speedup vs baseline: 2.4617x; 1.6814x over previous
#include <cuda_runtime.h>
#include <cuda_fp16.h>
#include <cstdint>

#define NN   40000
#define EE   640000
#define FH   128
#define GG   256
#define NOUT 10
#define NBLK ((NN + 255) / 256)   // 157

// ---------------- scratch (static device globals; no allocs) ----------------
__device__ int   g_count[NN];
__device__ int   g_ptr[NN + 1];
__device__ int   g_cursor[NN];
__device__ float g_dinv[NN];
__device__ int   g_src[EE];
__device__ int   g_blocksum[NBLK];
__device__ float g_buf0[(size_t)NN * FH];  // reused as half buffers
__device__ float g_buf1[(size_t)NN * FH];

__device__ __forceinline__ uint32_t h2u(__half2 h) { return *reinterpret_cast<uint32_t*>(&h); }
__device__ __forceinline__ __half2  u2h(uint32_t u) { return *reinterpret_cast<__half2*>(&u); }

// ---------------- CSR build ----------------
__global__ void k_zero_counts() {
    int i = blockIdx.x * blockDim.x + threadIdx.x;
    if (i < NN) g_count[i] = 0;
}

__global__ void k_hist(const int* __restrict__ ei) {
    int e = blockIdx.x * blockDim.x + threadIdx.x;
    if (e < EE) atomicAdd(&g_count[ei[EE + e]], 1);
}

// stage 1: per-block sums of g_count
__global__ void __launch_bounds__(256) k_block_reduce() {
    __shared__ int ws[8];
    int i = blockIdx.x * 256 + threadIdx.x;
    int v = (i < NN) ? g_count[i] : 0;
#pragma unroll
    for (int o = 16; o > 0; o >>= 1) v += __shfl_down_sync(0xffffffffu, v, o);
    if ((threadIdx.x & 31) == 0) ws[threadIdx.x >> 5] = v;
    __syncthreads();
    if (threadIdx.x < 8) {
        int s = ws[threadIdx.x];
#pragma unroll
        for (int o = 4; o > 0; o >>= 1) s += __shfl_down_sync(0xffu, s, o);
        if (threadIdx.x == 0) g_blocksum[blockIdx.x] = s;
    }
}

// stage 2: exclusive scan of the NBLK block sums (one small block)
__global__ void __launch_bounds__(256) k_block_offsets() {
    __shared__ int sm[256];
    int t = threadIdx.x;
    int v = (t < NBLK) ? g_blocksum[t] : 0;
    sm[t] = v;
    __syncthreads();
    for (int off = 1; off < 256; off <<= 1) {
        int u = (t >= off) ? sm[t - off] : 0;
        __syncthreads();
        sm[t] += u;
        __syncthreads();
    }
    if (t < NBLK) g_blocksum[t] = sm[t] - v;  // exclusive
}

// stage 3: per-block exclusive scan + block offset -> ptr/cursor/dinv
__global__ void __launch_bounds__(256) k_ptr_dinv() {
    __shared__ int ws[8];
    int t = threadIdx.x;
    int i = blockIdx.x * 256 + t;
    int c = (i < NN) ? g_count[i] : 0;
    int lane = t & 31, warp = t >> 5;

    int inc = c;
#pragma unroll
    for (int o = 1; o < 32; o <<= 1) {
        int u = __shfl_up_sync(0xffffffffu, inc, o);
        if (lane >= o) inc += u;
    }
    if (lane == 31) ws[warp] = inc;
    __syncthreads();
    if (t < 8) {
        int s = ws[t];
#pragma unroll
        for (int o = 1; o < 8; o <<= 1) {
            int u = __shfl_up_sync(0xffu, s, o);
            if (t >= o) s += u;
        }
        ws[t] = s;
    }
    __syncthreads();
    int ex = inc - c + (warp ? ws[warp - 1] : 0);  // block-exclusive prefix

    if (i < NN) {
        int p = g_blocksum[blockIdx.x] + ex;
        g_ptr[i]    = p;
        g_cursor[i] = p;
        g_dinv[i]   = rsqrtf((float)(c + 1));
        if (i == NN - 1) g_ptr[NN] = p + c;
    }
}

__global__ void k_scatter(const int* __restrict__ ei) {
    int e = blockIdx.x * blockDim.x + threadIdx.x;
    if (e < EE) {
        int c = ei[EE + e];
        int p = atomicAdd(&g_cursor[c], 1);
        g_src[p] = ei[e];
    }
}

// ---------------- fp16 mma GEMM: C[M,128](fp16) = A[M,128] @ W[128,128] ----------------
#define AHS 136
#define BHS 136
#define SMEM_GEMM ((128 * AHS + 128 * BHS) * 2)

__device__ __forceinline__ void mma_f16(float* c, uint32_t a0, uint32_t a1, uint32_t a2,
                                        uint32_t a3, uint32_t b0, uint32_t b1) {
    asm volatile(
        "mma.sync.aligned.m16n8k16.row.col.f32.f16.f16.f32 "
        "{%0,%1,%2,%3}, {%4,%5,%6,%7}, {%8,%9}, {%0,%1,%2,%3};"
        : "+f"(c[0]), "+f"(c[1]), "+f"(c[2]), "+f"(c[3])
        : "r"(a0), "r"(a1), "r"(a2), "r"(a3), "r"(b0), "r"(b1));
}

__global__ void __launch_bounds__(256, 2) k_gemm_h(
    const void* __restrict__ Ain, int a_fp32,
    const float* __restrict__ W, __half* __restrict__ C, int M) {
    extern __shared__ __half sh[];
    __half* As = sh;
    __half* Bs = sh + 128 * AHS;
    int tid = threadIdx.x;
    int row0 = blockIdx.x * 128;

    if (a_fp32) {
        const float* A = (const float*)Ain;
        for (int i = tid; i < 4096; i += 256) {
            int r = i >> 5, c = (i & 31) << 2;
            int gr = row0 + r;
            float4 v = make_float4(0.f, 0.f, 0.f, 0.f);
            if (gr < M) v = *(const float4*)(A + (size_t)gr * 128 + c);
            uint2 u;
            u.x = h2u(__floats2half2_rn(v.x, v.y));
            u.y = h2u(__floats2half2_rn(v.z, v.w));
            *(uint2*)(As + r * AHS + c) = u;
        }
    } else {
        const __half* A = (const __half*)Ain;
        for (int i = tid; i < 4096; i += 256) {
            int r = i >> 5, c = (i & 31) << 2;
            int gr = row0 + r;
            uint2 u = make_uint2(0u, 0u);
            if (gr < M) u = *(const uint2*)(A + (size_t)gr * 128 + c);
            *(uint2*)(As + r * AHS + c) = u;
        }
    }

    for (int t = 0; t < 8; t++) {
        int idx = tid + t * 256;
        int k2 = (idx & 31) | (((idx >> 5) & 1) << 5);
        int n4 = (idx >> 6) << 2;
        int k = k2 * 2;
        const float* w0 = W + (size_t)k * 128 + n4;
        float4 r0 = *(const float4*)w0;
        float4 r1 = *(const float4*)(w0 + 128);
        *(uint32_t*)(Bs + (n4 + 0) * BHS + k) = h2u(__floats2half2_rn(r0.x, r1.x));
        *(uint32_t*)(Bs + (n4 + 1) * BHS + k) = h2u(__floats2half2_rn(r0.y, r1.y));
        *(uint32_t*)(Bs + (n4 + 2) * BHS + k) = h2u(__floats2half2_rn(r0.z, r1.z));
        *(uint32_t*)(Bs + (n4 + 3) * BHS + k) = h2u(__floats2half2_rn(r0.w, r1.w));
    }
    __syncthreads();

    int wid = tid >> 5, lane = tid & 31;
    int wm = (wid >> 2) * 64;
    int wn = (wid & 3) * 32;
    int g = lane >> 2, tg = lane & 3;

    float acc[4][4][4];
#pragma unroll
    for (int mt = 0; mt < 4; mt++)
#pragma unroll
        for (int nt = 0; nt < 4; nt++)
#pragma unroll
            for (int r = 0; r < 4; r++) acc[mt][nt][r] = 0.f;

#pragma unroll
    for (int k0 = 0; k0 < 128; k0 += 16) {
        uint32_t af[4][4];
#pragma unroll
        for (int mt = 0; mt < 4; mt++) {
            const __half* ap = As + (wm + mt * 16) * AHS + k0 + tg * 2;
            af[mt][0] = *(const uint32_t*)(ap + g * AHS);
            af[mt][1] = *(const uint32_t*)(ap + (g + 8) * AHS);
            af[mt][2] = *(const uint32_t*)(ap + g * AHS + 8);
            af[mt][3] = *(const uint32_t*)(ap + (g + 8) * AHS + 8);
        }
        uint32_t bf[4][2];
#pragma unroll
        for (int nt = 0; nt < 4; nt++) {
            const __half* bp = Bs + (wn + nt * 8 + g) * BHS + k0 + tg * 2;
            bf[nt][0] = *(const uint32_t*)(bp);
            bf[nt][1] = *(const uint32_t*)(bp + 8);
        }
#pragma unroll
        for (int mt = 0; mt < 4; mt++)
#pragma unroll
            for (int nt = 0; nt < 4; nt++)
                mma_f16(acc[mt][nt], af[mt][0], af[mt][1], af[mt][2], af[mt][3],
                        bf[nt][0], bf[nt][1]);
    }

#pragma unroll
    for (int nt = 0; nt < 4; nt++) {
        int col = wn + nt * 8 + tg * 2;
#pragma unroll
        for (int mt = 0; mt < 4; mt++) {
            int r0 = row0 + wm + mt * 16 + g;
            if (r0 < M)
                *(uint32_t*)(C + (size_t)r0 * 128 + col) =
                    h2u(__floats2half2_rn(acc[mt][nt][0], acc[mt][nt][1]));
            int r1 = r0 + 8;
            if (r1 < M)
                *(uint32_t*)(C + (size_t)r1 * 128 + col) =
                    h2u(__floats2half2_rn(acc[mt][nt][2], acc[mt][nt][3]));
        }
    }
}

// ---------------- fp16 aggregation + bias + relu ----------------
__global__ void __launch_bounds__(256) k_agg_h(
    const __half* __restrict__ P, __half* __restrict__ Hout,
    const float* __restrict__ bias) {
    int warp = (blockIdx.x * blockDim.x + threadIdx.x) >> 5;
    int lane = threadIdx.x & 31;
    if (warp >= NN) return;
    int node = warp;
    int c4 = lane * 4;
    float di = g_dinv[node];

    uint2 sv = *(const uint2*)(P + (size_t)node * FH + c4);
    float2 f0 = __half22float2(u2h(sv.x));
    float2 f1 = __half22float2(u2h(sv.y));
    float ax = di * f0.x, ay = di * f0.y, az = di * f1.x, aw = di * f1.y;

    int beg = g_ptr[node], end = g_ptr[node + 1];
    int j = beg;
    for (; j + 4 <= end; j += 4) {
        int s0 = g_src[j], s1 = g_src[j + 1], s2 = g_src[j + 2], s3 = g_src[j + 3];
        float d0 = g_dinv[s0], d1 = g_dinv[s1], d2 = g_dinv[s2], d3 = g_dinv[s3];
        uint2 v0 = *(const uint2*)(P + (size_t)s0 * FH + c4);
        uint2 v1 = *(const uint2*)(P + (size_t)s1 * FH + c4);
        uint2 v2 = *(const uint2*)(P + (size_t)s2 * FH + c4);
        uint2 v3 = *(const uint2*)(P + (size_t)s3 * FH + c4);
        float2 a0 = __half22float2(u2h(v0.x)), b0 = __half22float2(u2h(v0.y));
        float2 a1 = __half22float2(u2h(v1.x)), b1 = __half22float2(u2h(v1.y));
        float2 a2 = __half22float2(u2h(v2.x)), b2 = __half22float2(u2h(v2.y));
        float2 a3 = __half22float2(u2h(v3.x)), b3 = __half22float2(u2h(v3.y));
        ax += d0 * a0.x + d1 * a1.x + d2 * a2.x + d3 * a3.x;
        ay += d0 * a0.y + d1 * a1.y + d2 * a2.y + d3 * a3.y;
        az += d0 * b0.x + d1 * b1.x + d2 * b2.x + d3 * b3.x;
        aw += d0 * b0.y + d1 * b1.y + d2 * b2.y + d3 * b3.y;
    }
    for (; j < end; j++) {
        int s0 = g_src[j];
        float d0 = g_dinv[s0];
        uint2 v0 = *(const uint2*)(P + (size_t)s0 * FH + c4);
        float2 a0 = __half22float2(u2h(v0.x)), b0 = __half22float2(u2h(v0.y));
        ax += d0 * a0.x; ay += d0 * a0.y; az += d0 * b0.x; aw += d0 * b0.y;
    }

    float4 bb = *(const float4*)(bias + c4);
    float ox = fmaxf(fmaf(ax, di, bb.x), 0.f);
    float oy = fmaxf(fmaf(ay, di, bb.y), 0.f);
    float oz = fmaxf(fmaf(az, di, bb.z), 0.f);
    float ow = fmaxf(fmaf(aw, di, bb.w), 0.f);
    uint2 o;
    o.x = h2u(__floats2half2_rn(ox, oy));
    o.y = h2u(__floats2half2_rn(oz, ow));
    *(uint2*)(Hout + (size_t)node * FH + c4) = o;
}

// ---------------- mean pool (batch sorted) + FC + log_softmax ----------------
__device__ __forceinline__ int lower_bound_i(const int* __restrict__ b, int n, int key) {
    int lo = 0, hi = n;
    while (lo < hi) {
        int mid = (lo + hi) >> 1;
        if (b[mid] < key) lo = mid + 1; else hi = mid;
    }
    return lo;
}

__global__ void __launch_bounds__(128) k_pool_fc(
    const __half* __restrict__ H2, const int* __restrict__ batch,
    const float* __restrict__ Wfc, const float* __restrict__ bfc,
    float* __restrict__ out) {
    int g = blockIdx.x;
    int tid = threadIdx.x;
    __shared__ float pooled[FH];
    __shared__ float logit[NOUT];
    __shared__ int range[2];

    if (tid == 0) {
        range[0] = lower_bound_i(batch, NN, g);
        range[1] = lower_bound_i(batch, NN, g + 1);
    }
    __syncthreads();
    int lo = range[0], hi = range[1];

    float s = 0.f;
    for (int n = lo; n < hi; n++) s += __half2float(H2[(size_t)n * FH + tid]);
    pooled[tid] = s / fmaxf((float)(hi - lo), 1.0f);
    __syncthreads();

    if (tid < NOUT) {
        float acc = bfc[tid];
        for (int k = 0; k < FH; k++) acc = fmaf(pooled[k], Wfc[k * NOUT + tid], acc);
        logit[tid] = acc;
    }
    __syncthreads();

    if (tid == 0) {
        float m = -1e30f;
        for (int o = 0; o < NOUT; o++) m = fmaxf(m, logit[o]);
        float se = 0.f;
        for (int o = 0; o < NOUT; o++) se += expf(logit[o] - m);
        float lse = m + logf(se);
        for (int o = 0; o < NOUT; o++) out[g * NOUT + o] = logit[o] - lse;
    }
}

// ---------------- launch ----------------
struct HxRes {
    cudaStream_t s2;
    cudaEvent_t e0, e1;
    HxRes() {
        cudaStreamCreateWithFlags(&s2, cudaStreamNonBlocking);
        cudaEventCreateWithFlags(&e0, cudaEventDisableTiming);
        cudaEventCreateWithFlags(&e1, cudaEventDisableTiming);
    }
};

extern "C" void kernel_launch(void* const* d_in, const int* in_sizes, int n_in,
                              void* d_out, int out_size) {
    static HxRes hx;

    const float* x    = (const float*)d_in[0];
    const int*   ei   = (const int*)d_in[1];
    const int*   batc = (const int*)d_in[2];
    const float* W1   = (const float*)d_in[3];
    const float* b1   = (const float*)d_in[4];
    const float* W2   = (const float*)d_in[5];
    const float* b2   = (const float*)d_in[6];
    const float* Wfc  = (const float*)d_in[7];
    const float* bfc  = (const float*)d_in[8];
    float* out = (float*)d_out;

    void *p0, *p1;
    cudaGetSymbolAddress(&p0, g_buf0);
    cudaGetSymbolAddress(&p1, g_buf1);
    __half* bufP = (__half*)p0;
    __half* bufH = (__half*)p1;

    cudaFuncSetAttribute(k_gemm_h,
                         cudaFuncAttributeMaxDynamicSharedMemorySize, SMEM_GEMM);

    int gblocks = (NN + 127) / 128;

    // fork: GEMM1 (P1 = X @ W1) independent of the CSR build
    cudaEventRecord(hx.e0, 0);
    cudaStreamWaitEvent(hx.s2, hx.e0, 0);
    k_gemm_h<<<gblocks, 256, SMEM_GEMM, hx.s2>>>(x, 1, W1, bufP, NN);
    cudaEventRecord(hx.e1, hx.s2);

    // CSR build on the main (capturing) stream — chip-wide scan
    k_zero_counts<<<NBLK, 256>>>();
    k_hist<<<(EE + 255) / 256, 256>>>(ei);
    k_block_reduce<<<NBLK, 256>>>();
    k_block_offsets<<<1, 256>>>();
    k_ptr_dinv<<<NBLK, 256>>>();
    k_scatter<<<(EE + 255) / 256, 256>>>(ei);

    // join, then: h1 = relu(agg(P1) + b1)
    cudaStreamWaitEvent(0, hx.e1, 0);
    k_agg_h<<<NN / 8, 256>>>(bufP, bufH, b1);

    // layer 2: P2 = h1 @ W2 ; h2 = relu(agg(P2) + b2)
    k_gemm_h<<<gblocks, 256, SMEM_GEMM>>>(bufH, 0, W2, bufP, NN);
    k_agg_h<<<NN / 8, 256>>>(bufP, bufH, b2);

    // mean pool + fc + log_softmax
    k_pool_fc<<<GG, 128>>>(bufH, batc, Wfc, bfc, out);
}